// round 6
// baseline (speedup 1.0000x reference)
#include <cuda_runtime.h>
#include <cuda_bf16.h>
#include <cstdint>

// ---------------------------------------------------------------------------
// CustomBLIP: sigmoid( relu( bilinear(img_n, txt_n; Wp) + bp ) @ Wc^T + bc )
// Core: feats[b,k] = sum_ij (img[b,i]*txt[b,j]) * Wp[k, i*512+j]
//   -> GEMM C[256,512] = A[256,262144] x Wp^T, A generated on the fly.
// R3: deep software pipeline (3-stage smem ring, 2-deep register staging,
//     8-iter img prefetch) to hide DRAM latency that bounded R2.
// ---------------------------------------------------------------------------

#define B_SZ   256
#define M_DIM  512
#define KIJ    (512 * 512)          // 262144
#define BKC    32                   // K-chunk (ij) per iter
#define ITERS  (KIJ / BKC)          // 8192
#define BM     128
#define BN     128
#define SPLITS 18

#define BSTR   20                   // Wp smem row stride in u32 (16 u32 + pad)
#define TSTR   260                  // txt smem row stride in u32 (256 + pad)

// smem layout (u32): Bs[3][BN*BSTR] | Ts[BM*TSTR] | img_s[2][128]
#define SM_BS_OFF   0
#define SM_TS_OFF   (3 * BN * BSTR)                 // 7680
#define SM_IMG_OFF  (SM_TS_OFF + BM * TSTR)         // 40960
#define SM_U32_TOT  (SM_IMG_OFF + 256)              // 41216
#define SM_BYTES    (SM_U32_TOT * 4)                // 164864

// -------------------------------- scratch ---------------------------------
__device__ float          g_pre[2 * B_SZ * M_DIM];
__device__ __nv_bfloat16  g_imgb[B_SZ * M_DIM];
__device__ __nv_bfloat16  g_txtb[B_SZ * M_DIM];
__device__ float          g_feats[B_SZ * M_DIM];

// -------------------------------- helpers ---------------------------------
__device__ __forceinline__ uint32_t u32_of(__nv_bfloat162 v) {
    return *reinterpret_cast<uint32_t*>(&v);
}
__device__ __forceinline__ __nv_bfloat162 bf2_of(uint32_t v) {
    return *reinterpret_cast<__nv_bfloat162*>(&v);
}
__device__ __forceinline__ uint32_t hmul2u(uint32_t a, uint32_t b) {
    __nv_bfloat162 r = __hmul2(bf2_of(a), bf2_of(b));
    return u32_of(r);
}
__device__ __forceinline__ uint32_t bpack(float lo, float hi) {
    __nv_bfloat162 h = __floats2bfloat162_rn(lo, hi);
    return u32_of(h);
}
__device__ __forceinline__ void mma16816(float* d, const uint32_t* a, const uint32_t* b) {
    asm volatile(
        "mma.sync.aligned.m16n8k16.row.col.f32.bf16.bf16.f32 "
        "{%0,%1,%2,%3}, {%4,%5,%6,%7}, {%8,%9}, {%0,%1,%2,%3};\n"
        : "+f"(d[0]), "+f"(d[1]), "+f"(d[2]), "+f"(d[3])
        : "r"(a[0]), "r"(a[1]), "r"(a[2]), "r"(a[3]), "r"(b[0]), "r"(b[1]));
}

// ----------------------- stage 1: mapping GEMMs (both paths) ----------------
__global__ __launch_bounds__(256) void map_gemm2(const float* __restrict__ Ximg,
                                                 const float* __restrict__ Xtxt,
                                                 const float* __restrict__ Wi,
                                                 const float* __restrict__ bi,
                                                 const float* __restrict__ Wt,
                                                 const float* __restrict__ bt) {
    __shared__ float Xs[32][33];
    __shared__ float Ws[32][33];
    int path = blockIdx.z;
    const float* X = path == 0 ? Ximg : Xtxt;
    const float* W = path == 0 ? Wi : Wt;
    const float* bias = path == 0 ? bi : bt;
    int tid = threadIdx.x;
    int tx = tid & 31, ty = tid >> 5;
    int mt = blockIdx.x, bt_ = blockIdx.y;
    float acc[4] = {0.f, 0.f, 0.f, 0.f};
    for (int d0 = 0; d0 < 512; d0 += 32) {
#pragma unroll
        for (int q = 0; q < 4; ++q) {
            int idx = tid + 256 * q;
            int r = idx >> 5, c = idx & 31;
            Xs[r][c] = X[(bt_ * 32 + r) * 512 + d0 + c];
            Ws[r][c] = W[(mt * 32 + r) * 512 + d0 + c];
        }
        __syncthreads();
#pragma unroll
        for (int kk = 0; kk < 32; ++kk) {
            float w = Ws[tx][kk];
#pragma unroll
            for (int r = 0; r < 4; ++r) acc[r] += Xs[ty + 8 * r][kk] * w;
        }
        __syncthreads();
    }
    float bb = bias[mt * 32 + tx];
#pragma unroll
    for (int r = 0; r < 4; ++r)
        g_pre[path * (B_SZ * M_DIM) + (bt_ * 32 + ty + 8 * r) * 512 + mt * 32 + tx] =
            acc[r] + bb;
}

// ----------------- stage 2: L2 normalize + bf16 cast + zero feats -----------
__global__ __launch_bounds__(128) void norm_zero() {
    int bx = blockIdx.x;
    int path = bx >> 8;
    int row = bx & 255;
    int t = threadIdx.x;
    const float* src = g_pre + path * (B_SZ * M_DIM) + row * 512;
    float v[4];
    float ss = 0.f;
#pragma unroll
    for (int q = 0; q < 4; ++q) {
        v[q] = src[t + 128 * q];
        ss += v[q] * v[q];
    }
#pragma unroll
    for (int o = 16; o > 0; o >>= 1) ss += __shfl_xor_sync(0xffffffffu, ss, o);
    __shared__ float sred[4];
    if ((t & 31) == 0) sred[t >> 5] = ss;
    __syncthreads();
    float tot = sred[0] + sred[1] + sred[2] + sred[3];
    float sc = 1.f / fmaxf(sqrtf(tot), 1e-12f);
    __nv_bfloat16* dst = (path == 0 ? g_imgb : g_txtb) + row * 512;
#pragma unroll
    for (int q = 0; q < 4; ++q) dst[t + 128 * q] = __float2bfloat16(v[q] * sc);
    if (path == 0) {
#pragma unroll
        for (int q = 0; q < 4; ++q) g_feats[row * 512 + t + 128 * q] = 0.f;
    }
}

// --------------------- stage 3: the big bilinear GEMM -----------------------
__device__ __forceinline__ void compute_iter(int it, const uint32_t* __restrict__ bs,
                                             const uint32_t* __restrict__ Ts,
                                             const uint32_t* __restrict__ imgb,
                                             const int* arow, int lane, int wn,
                                             float acc[4][4][4]) {
    int j0h = (it & 15) * 16;  // u32 offset of j0 within a txt row
    uint32_t im[8];
#pragma unroll
    for (int h = 0; h < 8; ++h) im[h] = imgb[arow[h]];
#pragma unroll
    for (int k2 = 0; k2 < 2; ++k2) {
        int co = j0h + k2 * 8 + (lane & 3);
        uint32_t a[4][4];
#pragma unroll
        for (int f = 0; f < 4; ++f) {
            uint32_t t0 = Ts[arow[2 * f] * TSTR + co];
            uint32_t t1 = Ts[arow[2 * f + 1] * TSTR + co];
            uint32_t t2 = Ts[arow[2 * f] * TSTR + co + 4];
            uint32_t t3 = Ts[arow[2 * f + 1] * TSTR + co + 4];
            a[f][0] = hmul2u(t0, im[2 * f]);
            a[f][1] = hmul2u(t1, im[2 * f + 1]);
            a[f][2] = hmul2u(t2, im[2 * f]);
            a[f][3] = hmul2u(t3, im[2 * f + 1]);
        }
        uint32_t bb[4][2];
#pragma unroll
        for (int g = 0; g < 4; ++g) {
            int n = wn * 32 + g * 8 + (lane >> 2);
            int base = n * BSTR + k2 * 8 + (lane & 3);
            bb[g][0] = bs[base];
            bb[g][1] = bs[base + 4];
        }
#pragma unroll
        for (int f = 0; f < 4; ++f)
#pragma unroll
            for (int g = 0; g < 4; ++g) mma16816(acc[f][g], a[f], bb[g]);
    }
}

__global__ __launch_bounds__(256) void bilinear_gemm(const float* __restrict__ Wp) {
    extern __shared__ uint32_t smem[];
    uint32_t* Bs = smem + SM_BS_OFF;
    uint32_t* Ts = smem + SM_TS_OFF;
    uint32_t* img_s = smem + SM_IMG_OFF;

    int tid = threadIdx.x;
    int lane = tid & 31, warp = tid >> 5;
    int wm = warp >> 2, wn = warp & 3;   // 2 x 4 warp grid, warp tile 64x32
    int s = blockIdx.x, nt = blockIdx.y, mt = blockIdx.z;
    int b0 = mt * BM, k0 = nt * BN;

    // ---- txt cache: 128 rows x 512 bf16 (256 u32/row, padded stride) ----
    {
        const uint32_t* src = reinterpret_cast<const uint32_t*>(g_txtb) + b0 * 256;
        for (int idx = tid; idx < BM * 256; idx += 256) {
            int r = idx >> 8, c = idx & 255;
            Ts[r * TSTR + c] = src[idx];
        }
    }

    int kb = (int)(((long)ITERS * s) / SPLITS);
    int ke = (int)(((long)ITERS * (s + 1)) / SPLITS);
    int n_it = ke - kb;

    float acc[4][4][4];
#pragma unroll
    for (int f = 0; f < 4; ++f)
#pragma unroll
        for (int g = 0; g < 4; ++g)
#pragma unroll
            for (int e = 0; e < 4; ++e) acc[f][g][e] = 0.f;

    // Wp staging: thread -> (rows wr+32u, float4 segment wseg)
    int wr = tid >> 3, wseg = tid & 7;
    const float* wp_row[4];
#pragma unroll
    for (int u = 0; u < 4; ++u)
        wp_row[u] = Wp + (size_t)(k0 + wr + 32 * u) * KIJ + wseg * 4;

    float4 stA[4], stB[4];   // two register staging sets (compile-time indexed)
    uint32_t ireg = 0;       // img column prefetch register

    int arow[8];
#pragma unroll
    for (int f = 0; f < 4; ++f) {
        arow[2 * f] = wm * 64 + f * 16 + (lane >> 2);
        arow[2 * f + 1] = arow[2 * f] + 8;
    }

#define LDG_SET(SET, chunk)                                                  \
    do {                                                                     \
        size_t ij_ = (size_t)(chunk) * BKC;                                  \
        _Pragma("unroll") for (int u = 0; u < 4; ++u)                        \
            SET[u] = *reinterpret_cast<const float4*>(wp_row[u] + ij_);      \
    } while (0)

#define STS_SET(SET, BUF)                                                    \
    do {                                                                     \
        uint32_t* d_ = Bs + (BUF) * (BN * BSTR);                             \
        _Pragma("unroll") for (int u = 0; u < 4; ++u) {                      \
            uint2 v_;                                                        \
            v_.x = bpack(SET[u].x, SET[u].y);                                \
            v_.y = bpack(SET[u].z, SET[u].w);                                \
            *reinterpret_cast<uint2*>(&d_[(wr + 32 * u) * BSTR + wseg * 2])  \
                = v_;                                                        \
        }                                                                    \
    } while (0)

#define IMG_STEP(it_)                                                        \
    do {                                                                     \
        if (((it_) & 15) == 0) {                                             \
            int c_ = ((it_) >> 4) + 1;                                       \
            if (c_ < 512 && tid < 128)                                       \
                ireg = u32_of(__bfloat162bfloat162(                          \
                    g_imgb[(b0 + tid) * 512 + c_]));                         \
        }                                                                    \
        if (((it_) & 15) == 8) {                                             \
            int c_ = ((it_) >> 4) + 1;                                       \
            if (c_ < 512 && tid < 128) img_s[(c_ & 1) * 128 + tid] = ireg;   \
        }                                                                    \
    } while (0)

    // ---- prologue ----
    int bc = kb % 3;  // buffer holding current chunk
    {
        LDG_SET(stA, kb);                      // chunk kb
        if (n_it > 1) LDG_SET(stB, kb + 1);    // chunk kb+1
        STS_SET(stA, bc);
        int i0 = kb >> 4;
        if (tid < 128) {
            img_s[(i0 & 1) * 128 + tid] =
                u32_of(__bfloat162bfloat162(g_imgb[(b0 + tid) * 512 + i0]));
            if (i0 + 1 < 512) {
                ireg = u32_of(__bfloat162bfloat162(
                    g_imgb[(b0 + tid) * 512 + i0 + 1]));
                img_s[((i0 + 1) & 1) * 128 + tid] = ireg;
            }
        }
    }
    __syncthreads();

    // ---- main loop, 2x unrolled so register-set roles are compile-time ----
    int r = 0;
#pragma unroll 1
    while (r < n_it) {
        {   // even r: stA holds chunk it (already stored); LDG it+2 -> stA
            int it = kb + r;
            int bn = bc + 1; if (bn == 3) bn = 0;
            if (it + 2 < ke) LDG_SET(stA, it + 2);
            if (it + 1 < ke) STS_SET(stB, bn);
            IMG_STEP(it);
            compute_iter(it, Bs + bc * (BN * BSTR), Ts,
                         img_s + ((it >> 4) & 1) * 128, arow, lane, wn, acc);
            __syncthreads();
            bc = bn;
        }
        ++r;
        if (r >= n_it) break;
        {   // odd r: stB holds chunk it (already stored); LDG it+2 -> stB
            int it = kb + r;
            int bn = bc + 1; if (bn == 3) bn = 0;
            if (it + 2 < ke) LDG_SET(stB, it + 2);
            if (it + 1 < ke) STS_SET(stA, bn);
            IMG_STEP(it);
            compute_iter(it, Bs + bc * (BN * BSTR), Ts,
                         img_s + ((it >> 4) & 1) * 128, arow, lane, wn, acc);
            __syncthreads();
            bc = bn;
        }
        ++r;
    }

    // ---- split-K epilogue: accumulate partials into g_feats ----
#pragma unroll
    for (int f = 0; f < 4; ++f)
#pragma unroll
        for (int g = 0; g < 4; ++g)
#pragma unroll
            for (int e = 0; e < 4; ++e) {
                int rr = b0 + wm * 64 + f * 16 + (lane >> 2) + ((e >> 1) << 3);
                int cc = k0 + wn * 32 + g * 8 + ((lane & 3) << 1) + (e & 1);
                atomicAdd(&g_feats[rr * 512 + cc], acc[f][g][e]);
            }
#undef LDG_SET
#undef STS_SET
#undef IMG_STEP
}

// ------------------ stage 4: bias + relu + classifier + sigmoid -------------
__global__ __launch_bounds__(128) void final_k(const float* __restrict__ bp,
                                               const float* __restrict__ Wc,
                                               const float* __restrict__ bc,
                                               float* __restrict__ out) {
    int b = blockIdx.x;
    int t = threadIdx.x;
    float p = 0.f;
    for (int k = t; k < 512; k += 128) {
        float f = g_feats[b * 512 + k] + bp[k];
        f = fmaxf(f, 0.f);
        p += f * Wc[k];
    }
#pragma unroll
    for (int o = 16; o > 0; o >>= 1) p += __shfl_xor_sync(0xffffffffu, p, o);
    __shared__ float sr[4];
    if ((t & 31) == 0) sr[t >> 5] = p;
    __syncthreads();
    if (t == 0) {
        float logit = sr[0] + sr[1] + sr[2] + sr[3] + bc[0];
        out[b] = 1.f / (1.f + expf(-logit));
    }
}

// ------------------------------ launcher ------------------------------------
extern "C" void kernel_launch(void* const* d_in, const int* in_sizes, int n_in,
                              void* d_out, int out_size) {
    const float* img_e = (const float*)d_in[0];
    const float* txt_e = (const float*)d_in[1];
    const float* Wi = (const float*)d_in[2];
    const float* bi = (const float*)d_in[3];
    const float* Wt = (const float*)d_in[4];
    const float* bt = (const float*)d_in[5];
    const float* Wp = (const float*)d_in[6];
    const float* bp = (const float*)d_in[7];
    const float* Wc = (const float*)d_in[8];
    const float* bc = (const float*)d_in[9];
    float* out = (float*)d_out;

    cudaFuncSetAttribute(bilinear_gemm, cudaFuncAttributeMaxDynamicSharedMemorySize,
                         SM_BYTES);

    map_gemm2<<<dim3(16, 8, 2), 256>>>(img_e, txt_e, Wi, bi, Wt, bt);
    norm_zero<<<512, 128>>>();
    bilinear_gemm<<<dim3(SPLITS, 4, 2), 256, SM_BYTES>>>(Wp);
    final_k<<<256, 128>>>(bp, Wc, bc, out);
}

// round 7
// speedup vs baseline: 1.7782x; 1.7782x over previous
#include <cuda_runtime.h>
#include <cuda_bf16.h>
#include <cstdint>

// ---------------------------------------------------------------------------
// CustomBLIP: sigmoid( relu( bilinear(img_n, txt_n; Wp) + bp ) @ Wc^T + bc )
// Core: feats[b,k] = sum_ij (img[b,i]*txt[b,j]) * Wp[k, i*512+j]
//   -> GEMM C[256,512] = A[256,262144] x Wp^T, A generated on the fly.
// R6: cp.async 4-stage fp32 ring for Wp (no register staging, no convert on
//     the load path); fragments converted fp32->bf16 in-register before
//     mma.m16n8k16.bf16. Fixes the latency exposure that bounded R2/R3.
// ---------------------------------------------------------------------------

#define B_SZ   256
#define M_DIM  512
#define KIJ    (512 * 512)          // 262144
#define BKC    32                   // K-chunk (ij) per iter
#define ITERS  (KIJ / BKC)          // 8192
#define BM     128
#define BN     128
#define SPLITS 18

#define NSTG    4                   // cp.async pipeline stages
#define BSF     40                  // Wp smem row stride in fp32 (32 + pad)
#define STG_U32 (BN * BSF)          // 5120 u32 per stage
#define TSTR    260                 // txt smem row stride in u32 (256 + pad)

// smem layout (u32): Bs[4][STG_U32] | Ts[BM*TSTR] | img_s[2][128]
#define SM_TS_OFF   (NSTG * STG_U32)                // 20480
#define SM_IMG_OFF  (SM_TS_OFF + BM * TSTR)         // 53760
#define SM_U32_TOT  (SM_IMG_OFF + 256)              // 54016
#define SM_BYTES    (SM_U32_TOT * 4)                // 216064

// -------------------------------- scratch ---------------------------------
__device__ float                         g_pre[2 * B_SZ * M_DIM];
__device__ __align__(16) __nv_bfloat16   g_imgb[B_SZ * M_DIM];
__device__ __align__(16) __nv_bfloat16   g_txtb[B_SZ * M_DIM];
__device__ float                         g_feats[B_SZ * M_DIM];

// -------------------------------- helpers ---------------------------------
__device__ __forceinline__ uint32_t u32_of(__nv_bfloat162 v) {
    return *reinterpret_cast<uint32_t*>(&v);
}
__device__ __forceinline__ __nv_bfloat162 bf2_of(uint32_t v) {
    return *reinterpret_cast<__nv_bfloat162*>(&v);
}
__device__ __forceinline__ uint32_t hmul2u(uint32_t a, uint32_t b) {
    __nv_bfloat162 r = __hmul2(bf2_of(a), bf2_of(b));
    return u32_of(r);
}
__device__ __forceinline__ uint32_t bpack(float lo, float hi) {
    __nv_bfloat162 h = __floats2bfloat162_rn(lo, hi);
    return u32_of(h);
}
__device__ __forceinline__ uint32_t smem_u32(const void* p) {
    uint32_t a;
    asm("{ .reg .u64 t; cvta.to.shared.u64 t, %1; cvt.u32.u64 %0, t; }"
        : "=r"(a) : "l"(p));
    return a;
}
__device__ __forceinline__ void mma16816(float* d, const uint32_t* a, const uint32_t* b) {
    asm volatile(
        "mma.sync.aligned.m16n8k16.row.col.f32.bf16.bf16.f32 "
        "{%0,%1,%2,%3}, {%4,%5,%6,%7}, {%8,%9}, {%0,%1,%2,%3};\n"
        : "+f"(d[0]), "+f"(d[1]), "+f"(d[2]), "+f"(d[3])
        : "r"(a[0]), "r"(a[1]), "r"(a[2]), "r"(a[3]), "r"(b[0]), "r"(b[1]));
}

// ----------------------- stage 1: mapping GEMMs (both paths) ----------------
__global__ __launch_bounds__(256) void map_gemm2(const float* __restrict__ Ximg,
                                                 const float* __restrict__ Xtxt,
                                                 const float* __restrict__ Wi,
                                                 const float* __restrict__ bi,
                                                 const float* __restrict__ Wt,
                                                 const float* __restrict__ bt) {
    __shared__ float Xs[32][33];
    __shared__ float Ws[32][33];
    int path = blockIdx.z;
    const float* X = path == 0 ? Ximg : Xtxt;
    const float* W = path == 0 ? Wi : Wt;
    const float* bias = path == 0 ? bi : bt;
    int tid = threadIdx.x;
    int tx = tid & 31, ty = tid >> 5;
    int mt = blockIdx.x, bt_ = blockIdx.y;
    float acc[4] = {0.f, 0.f, 0.f, 0.f};
    for (int d0 = 0; d0 < 512; d0 += 32) {
#pragma unroll
        for (int q = 0; q < 4; ++q) {
            int idx = tid + 256 * q;
            int r = idx >> 5, c = idx & 31;
            Xs[r][c] = X[(bt_ * 32 + r) * 512 + d0 + c];
            Ws[r][c] = W[(mt * 32 + r) * 512 + d0 + c];
        }
        __syncthreads();
#pragma unroll
        for (int kk = 0; kk < 32; ++kk) {
            float w = Ws[tx][kk];
#pragma unroll
            for (int r = 0; r < 4; ++r) acc[r] += Xs[ty + 8 * r][kk] * w;
        }
        __syncthreads();
    }
    float bb = bias[mt * 32 + tx];
#pragma unroll
    for (int r = 0; r < 4; ++r)
        g_pre[path * (B_SZ * M_DIM) + (bt_ * 32 + ty + 8 * r) * 512 + mt * 32 + tx] =
            acc[r] + bb;
}

// ----------------- stage 2: L2 normalize + bf16 cast + zero feats -----------
__global__ __launch_bounds__(128) void norm_zero() {
    int bx = blockIdx.x;
    int path = bx >> 8;
    int row = bx & 255;
    int t = threadIdx.x;
    const float* src = g_pre + path * (B_SZ * M_DIM) + row * 512;
    float v[4];
    float ss = 0.f;
#pragma unroll
    for (int q = 0; q < 4; ++q) {
        v[q] = src[t + 128 * q];
        ss += v[q] * v[q];
    }
#pragma unroll
    for (int o = 16; o > 0; o >>= 1) ss += __shfl_xor_sync(0xffffffffu, ss, o);
    __shared__ float sred[4];
    if ((t & 31) == 0) sred[t >> 5] = ss;
    __syncthreads();
    float tot = sred[0] + sred[1] + sred[2] + sred[3];
    float sc = 1.f / fmaxf(sqrtf(tot), 1e-12f);
    __nv_bfloat16* dst = (path == 0 ? g_imgb : g_txtb) + row * 512;
#pragma unroll
    for (int q = 0; q < 4; ++q) dst[t + 128 * q] = __float2bfloat16(v[q] * sc);
    if (path == 0) {
#pragma unroll
        for (int q = 0; q < 4; ++q) g_feats[row * 512 + t + 128 * q] = 0.f;
    }
}

// --------------------- stage 3: the big bilinear GEMM -----------------------
__device__ __forceinline__ void compute_iter(int it, const float* __restrict__ bsf,
                                             const uint32_t* __restrict__ Ts,
                                             const uint32_t* __restrict__ imgb,
                                             const int* arow, int lane, int wn,
                                             float acc[4][4][4]) {
    int j0h = (it & 15) * 16;  // u32 offset of j0 within a txt row
    uint32_t im[8];
#pragma unroll
    for (int h = 0; h < 8; ++h) im[h] = imgb[arow[h]];
#pragma unroll
    for (int k2 = 0; k2 < 2; ++k2) {
        int co = j0h + k2 * 8 + (lane & 3);
        uint32_t a[4][4];
#pragma unroll
        for (int f = 0; f < 4; ++f) {
            uint32_t t0 = Ts[arow[2 * f] * TSTR + co];
            uint32_t t1 = Ts[arow[2 * f + 1] * TSTR + co];
            uint32_t t2 = Ts[arow[2 * f] * TSTR + co + 4];
            uint32_t t3 = Ts[arow[2 * f + 1] * TSTR + co + 4];
            a[f][0] = hmul2u(t0, im[2 * f]);
            a[f][1] = hmul2u(t1, im[2 * f + 1]);
            a[f][2] = hmul2u(t2, im[2 * f]);
            a[f][3] = hmul2u(t3, im[2 * f + 1]);
        }
        uint32_t bb[4][2];
#pragma unroll
        for (int g = 0; g < 4; ++g) {
            int n = wn * 32 + g * 8 + (lane >> 2);
            const float* p = bsf + n * BSF + k2 * 16 + (lane & 3) * 2;
            float2 v0 = *reinterpret_cast<const float2*>(p);
            float2 v1 = *reinterpret_cast<const float2*>(p + 8);
            bb[g][0] = bpack(v0.x, v0.y);
            bb[g][1] = bpack(v1.x, v1.y);
        }
#pragma unroll
        for (int f = 0; f < 4; ++f)
#pragma unroll
            for (int g = 0; g < 4; ++g) mma16816(acc[f][g], a[f], bb[g]);
    }
}

__global__ __launch_bounds__(256) void bilinear_gemm(const float* __restrict__ Wp) {
    extern __shared__ uint32_t smem[];
    float* Bsf = reinterpret_cast<float*>(smem);
    uint32_t* Ts = smem + SM_TS_OFF;
    uint32_t* img_s = smem + SM_IMG_OFF;

    int tid = threadIdx.x;
    int lane = tid & 31, warp = tid >> 5;
    int wm = warp >> 2, wn = warp & 3;   // 2 x 4 warp grid, warp tile 64x32
    int s = blockIdx.x, nt = blockIdx.y, mt = blockIdx.z;
    int b0 = mt * BM, k0 = nt * BN;

    int kb = (int)(((long)ITERS * s) / SPLITS);
    int ke = (int)(((long)ITERS * (s + 1)) / SPLITS);

    // ---- cp.async assignment: thread -> 4 x 16B per chunk ----
    // op o = tid + 256*u : row = o>>3 = (tid>>3)+32u, seg = tid&7
    int crow = tid >> 3, cseg = tid & 7;
    const float* wp_src[4];
    uint32_t sm_off[4];                       // byte offsets within a stage
#pragma unroll
    for (int u = 0; u < 4; ++u) {
        int row = crow + 32 * u;
        wp_src[u] = Wp + (size_t)(k0 + row) * KIJ + cseg * 4;
        sm_off[u] = (uint32_t)(row * BSF + cseg * 4) * 4u;
    }
    uint32_t bs_addr = smem_u32(smem);        // byte address of stage 0

#define CPY(chunk)                                                            \
    do {                                                                      \
        if ((chunk) < ke) {                                                   \
            uint32_t sa_ = bs_addr + (uint32_t)(((chunk) & (NSTG - 1)) *      \
                                                (STG_U32 * 4));               \
            _Pragma("unroll") for (int u_ = 0; u_ < 4; ++u_) {                \
                const float* gp_ = wp_src[u_] + (size_t)(chunk) * BKC;        \
                asm volatile("cp.async.cg.shared.global [%0], [%1], 16;"      \
                             :: "r"(sa_ + sm_off[u_]), "l"(gp_));             \
            }                                                                 \
        }                                                                     \
        asm volatile("cp.async.commit_group;" ::: "memory");                  \
    } while (0)

#define IMG_STEP(it_)                                                         \
    do {                                                                      \
        if (((it_) & 15) == 0) {                                              \
            int c_ = ((it_) >> 4) + 1;                                        \
            if (c_ < 512 && tid < 128)                                        \
                ireg = u32_of(__bfloat162bfloat162(                           \
                    g_imgb[(b0 + tid) * 512 + c_]));                          \
        }                                                                     \
        if (((it_) & 15) == 8) {                                              \
            int c_ = ((it_) >> 4) + 1;                                        \
            if (c_ < 512 && tid < 128) img_s[(c_ & 1) * 128 + tid] = ireg;    \
        }                                                                     \
    } while (0)

    // ---- prologue: launch first 3 chunks, then fill txt + img caches ----
    CPY(kb);
    CPY(kb + 1);
    CPY(kb + 2);

    {   // txt cache: 128 rows x 512 bf16, uint4 copies
        const uint4* src = reinterpret_cast<const uint4*>(g_txtb) + b0 * 64;
        for (int idx = tid; idx < BM * 64; idx += 256) {
            int r = idx >> 6, c4 = idx & 63;
            *reinterpret_cast<uint4*>(&Ts[r * TSTR + c4 * 4]) = src[r * 64 + c4];
        }
    }

    uint32_t ireg = 0;
    {   // img prologue: columns i0 and i0+1
        int i0 = kb >> 4;
        if (tid < 128) {
            img_s[(i0 & 1) * 128 + tid] =
                u32_of(__bfloat162bfloat162(g_imgb[(b0 + tid) * 512 + i0]));
            if (i0 + 1 < 512) {
                ireg = u32_of(__bfloat162bfloat162(
                    g_imgb[(b0 + tid) * 512 + i0 + 1]));
                img_s[((i0 + 1) & 1) * 128 + tid] = ireg;
            }
        }
    }

    float acc[4][4][4];
#pragma unroll
    for (int f = 0; f < 4; ++f)
#pragma unroll
        for (int g = 0; g < 4; ++g)
#pragma unroll
            for (int e = 0; e < 4; ++e) acc[f][g][e] = 0.f;

    int arow[8];
#pragma unroll
    for (int f = 0; f < 4; ++f) {
        arow[2 * f] = wm * 64 + f * 16 + (lane >> 2);
        arow[2 * f + 1] = arow[2 * f] + 8;
    }

    // ---- main loop: 1 sync/iter, cp.async depth 3 ----
#pragma unroll 1
    for (int it = kb; it < ke; ++it) {
        asm volatile("cp.async.wait_group 2;" ::: "memory");
        __syncthreads();
        CPY(it + 3);
        IMG_STEP(it);
        compute_iter(it, Bsf + (it & (NSTG - 1)) * STG_U32, Ts,
                     img_s + ((it >> 4) & 1) * 128, arow, lane, wn, acc);
    }
    asm volatile("cp.async.wait_group 0;" ::: "memory");

    // ---- split-K epilogue: accumulate partials into g_feats ----
#pragma unroll
    for (int f = 0; f < 4; ++f)
#pragma unroll
        for (int g = 0; g < 4; ++g)
#pragma unroll
            for (int e = 0; e < 4; ++e) {
                int rr = b0 + wm * 64 + f * 16 + (lane >> 2) + ((e >> 1) << 3);
                int cc = k0 + wn * 32 + g * 8 + ((lane & 3) << 1) + (e & 1);
                atomicAdd(&g_feats[rr * 512 + cc], acc[f][g][e]);
            }
#undef CPY
#undef IMG_STEP
}

// ------------------ stage 4: bias + relu + classifier + sigmoid -------------
__global__ __launch_bounds__(128) void final_k(const float* __restrict__ bp,
                                               const float* __restrict__ Wc,
                                               const float* __restrict__ bc,
                                               float* __restrict__ out) {
    int b = blockIdx.x;
    int t = threadIdx.x;
    float p = 0.f;
    for (int k = t; k < 512; k += 128) {
        float f = g_feats[b * 512 + k] + bp[k];
        f = fmaxf(f, 0.f);
        p += f * Wc[k];
    }
#pragma unroll
    for (int o = 16; o > 0; o >>= 1) p += __shfl_xor_sync(0xffffffffu, p, o);
    __shared__ float sr[4];
    if ((t & 31) == 0) sr[t >> 5] = p;
    __syncthreads();
    if (t == 0) {
        float logit = sr[0] + sr[1] + sr[2] + sr[3] + bc[0];
        out[b] = 1.f / (1.f + expf(-logit));
    }
}

// ------------------------------ launcher ------------------------------------
extern "C" void kernel_launch(void* const* d_in, const int* in_sizes, int n_in,
                              void* d_out, int out_size) {
    const float* img_e = (const float*)d_in[0];
    const float* txt_e = (const float*)d_in[1];
    const float* Wi = (const float*)d_in[2];
    const float* bi = (const float*)d_in[3];
    const float* Wt = (const float*)d_in[4];
    const float* bt = (const float*)d_in[5];
    const float* Wp = (const float*)d_in[6];
    const float* bp = (const float*)d_in[7];
    const float* Wc = (const float*)d_in[8];
    const float* bc = (const float*)d_in[9];
    float* out = (float*)d_out;

    cudaFuncSetAttribute(bilinear_gemm, cudaFuncAttributeMaxDynamicSharedMemorySize,
                         SM_BYTES);

    map_gemm2<<<dim3(16, 8, 2), 256>>>(img_e, txt_e, Wi, bi, Wt, bt);
    norm_zero<<<512, 128>>>();
    bilinear_gemm<<<dim3(SPLITS, 4, 2), 256, SM_BYTES>>>(Wp);
    final_k<<<256, 128>>>(bp, Wc, bc, out);
}

// round 9
// speedup vs baseline: 2.2241x; 1.2508x over previous
#include <cuda_runtime.h>
#include <cuda_bf16.h>
#include <cstdint>

// ---------------------------------------------------------------------------
// CustomBLIP: sigmoid( relu( bilinear(img_n, txt_n; Wp) + bp ) @ Wc^T + bc )
// Core: feats[b,k] = sum_ij (img[b,i]*txt[b,j]) * Wp[k, i*512+j]
//   -> GEMM C[256,512] = A[256,262144] x Wp^T, A generated on the fly.
// R8: j-block-major chunk order -> txt smem cache shrinks 130KB -> 10KB,
//     img becomes per-iter coalesced 512B LDG (2-iter prefetch ring).
//     93KB smem/CTA + <=128 regs -> 2 CTAs/SM (SPLITS=37, 296 CTAs).
// ---------------------------------------------------------------------------

#define B_SZ   256
#define M_DIM  512
#define KIJ    (512 * 512)          // 262144
#define ITERS  8192                 // chunks of 32 ij
#define BM     128
#define BN     128
#define SPLITS 37                   // 37*4*2 = 296 CTAs = 2/SM

#define NSTG    4                   // cp.async stages
#define BSF     40                  // Wp smem row stride in fp32 (32 + pad)
#define STG_U32 (BN * BSF)          // 5120 u32 per stage
#define TSTR    20                  // txt smem row stride in u32 (16 + pad)

// smem layout (u32): Bs[4][STG_U32] | Ts[128*TSTR] | img_s[2][128]
#define SM_TS_OFF   (NSTG * STG_U32)                // 20480
#define SM_IMG_OFF  (SM_TS_OFF + BM * TSTR)         // 23040
#define SM_U32_TOT  (SM_IMG_OFF + 256)              // 23296
#define SM_BYTES    (SM_U32_TOT * 4)                // 93184  (2 CTAs/SM)

// -------------------------------- scratch ---------------------------------
__device__ float                        g_pre[2 * B_SZ * M_DIM];
__device__ uint32_t                     g_imgu[M_DIM * B_SZ];  // [i][b] bf16x2 bcast
__device__ __align__(16) __nv_bfloat16  g_txtb[B_SZ * M_DIM];  // [b][j]
__device__ float                        g_feats[B_SZ * M_DIM];

// -------------------------------- helpers ---------------------------------
__device__ __forceinline__ uint32_t u32_of(__nv_bfloat162 v) {
    return *reinterpret_cast<uint32_t*>(&v);
}
__device__ __forceinline__ __nv_bfloat162 bf2_of(uint32_t v) {
    return *reinterpret_cast<__nv_bfloat162*>(&v);
}
__device__ __forceinline__ uint32_t hmul2u(uint32_t a, uint32_t b) {
    __nv_bfloat162 r = __hmul2(bf2_of(a), bf2_of(b));
    return u32_of(r);
}
__device__ __forceinline__ uint32_t bpack(float lo, float hi) {
    __nv_bfloat162 h = __floats2bfloat162_rn(lo, hi);
    return u32_of(h);
}
__device__ __forceinline__ uint32_t smem_u32(const void* p) {
    uint32_t a;
    asm("{ .reg .u64 t; cvta.to.shared.u64 t, %1; cvt.u32.u64 %0, t; }"
        : "=r"(a) : "l"(p));
    return a;
}
__device__ __forceinline__ void mma16816(float* d, const uint32_t* a, const uint32_t* b) {
    asm volatile(
        "mma.sync.aligned.m16n8k16.row.col.f32.bf16.bf16.f32 "
        "{%0,%1,%2,%3}, {%4,%5,%6,%7}, {%8,%9}, {%0,%1,%2,%3};\n"
        : "+f"(d[0]), "+f"(d[1]), "+f"(d[2]), "+f"(d[3])
        : "r"(a[0]), "r"(a[1]), "r"(a[2]), "r"(a[3]), "r"(b[0]), "r"(b[1]));
}

// ----------------------- stage 1: mapping GEMMs (both paths) ----------------
__global__ __launch_bounds__(256) void map_gemm2(const float* __restrict__ Ximg,
                                                 const float* __restrict__ Xtxt,
                                                 const float* __restrict__ Wi,
                                                 const float* __restrict__ bi,
                                                 const float* __restrict__ Wt,
                                                 const float* __restrict__ bt) {
    __shared__ float Xs[32][33];
    __shared__ float Ws[32][33];
    int path = blockIdx.z;
    const float* X = path == 0 ? Ximg : Xtxt;
    const float* W = path == 0 ? Wi : Wt;
    const float* bias = path == 0 ? bi : bt;
    int tid = threadIdx.x;
    int tx = tid & 31, ty = tid >> 5;
    int mt = blockIdx.x, bt_ = blockIdx.y;
    float acc[4] = {0.f, 0.f, 0.f, 0.f};
    for (int d0 = 0; d0 < 512; d0 += 32) {
#pragma unroll
        for (int q = 0; q < 4; ++q) {
            int idx = tid + 256 * q;
            int r = idx >> 5, c = idx & 31;
            Xs[r][c] = X[(bt_ * 32 + r) * 512 + d0 + c];
            Ws[r][c] = W[(mt * 32 + r) * 512 + d0 + c];
        }
        __syncthreads();
#pragma unroll
        for (int kk = 0; kk < 32; ++kk) {
            float w = Ws[tx][kk];
#pragma unroll
            for (int r = 0; r < 4; ++r) acc[r] += Xs[ty + 8 * r][kk] * w;
        }
        __syncthreads();
    }
    float bb = bias[mt * 32 + tx];
#pragma unroll
    for (int r = 0; r < 4; ++r)
        g_pre[path * (B_SZ * M_DIM) + (bt_ * 32 + ty + 8 * r) * 512 + mt * 32 + tx] =
            acc[r] + bb;
}

// ----- stage 2: L2 normalize; img -> transposed bf16x2 table; txt -> bf16 ---
__global__ __launch_bounds__(128) void norm_zero() {
    int bx = blockIdx.x;
    int path = bx >> 8;
    int row = bx & 255;
    int t = threadIdx.x;
    const float* src = g_pre + path * (B_SZ * M_DIM) + row * 512;
    float v[4];
    float ss = 0.f;
#pragma unroll
    for (int q = 0; q < 4; ++q) {
        v[q] = src[t + 128 * q];
        ss += v[q] * v[q];
    }
#pragma unroll
    for (int o = 16; o > 0; o >>= 1) ss += __shfl_xor_sync(0xffffffffu, ss, o);
    __shared__ float sred[4];
    if ((t & 31) == 0) sred[t >> 5] = ss;
    __syncthreads();
    float tot = sred[0] + sred[1] + sred[2] + sred[3];
    float sc = 1.f / fmaxf(sqrtf(tot), 1e-12f);
    if (path == 0) {
#pragma unroll
        for (int q = 0; q < 4; ++q) {
            float val = v[q] * sc;
            g_imgu[(t + 128 * q) * 256 + row] = bpack(val, val);
            g_feats[row * 512 + t + 128 * q] = 0.f;
        }
    } else {
#pragma unroll
        for (int q = 0; q < 4; ++q)
            g_txtb[row * 512 + t + 128 * q] = __float2bfloat16(v[q] * sc);
    }
}

// --------------------- stage 3: the big bilinear GEMM -----------------------
// chunk c in [0,8192): i = c & 511 (fast), jblk = c >> 9 (slow, 16 blocks)
__device__ __forceinline__ void compute_iter(const float* __restrict__ bsf,
                                             const uint32_t* __restrict__ Ts,
                                             const uint32_t* __restrict__ imgcol,
                                             const int* arow, int lane, int wn,
                                             float acc[4][4][4]) {
    uint32_t im[8];
#pragma unroll
    for (int h = 0; h < 8; ++h) im[h] = imgcol[arow[h]];
#pragma unroll
    for (int k2 = 0; k2 < 2; ++k2) {
        int co = k2 * 8 + (lane & 3);
        uint32_t a[4][4];
#pragma unroll
        for (int f = 0; f < 4; ++f) {
            uint32_t t0 = Ts[arow[2 * f] * TSTR + co];
            uint32_t t1 = Ts[arow[2 * f + 1] * TSTR + co];
            uint32_t t2 = Ts[arow[2 * f] * TSTR + co + 4];
            uint32_t t3 = Ts[arow[2 * f + 1] * TSTR + co + 4];
            a[f][0] = hmul2u(t0, im[2 * f]);
            a[f][1] = hmul2u(t1, im[2 * f + 1]);
            a[f][2] = hmul2u(t2, im[2 * f]);
            a[f][3] = hmul2u(t3, im[2 * f + 1]);
        }
        uint32_t bb[4][2];
#pragma unroll
        for (int g = 0; g < 4; ++g) {
            int n = wn * 32 + g * 8 + (lane >> 2);
            const float* p = bsf + n * BSF + k2 * 16 + (lane & 3) * 2;
            float2 v0 = *reinterpret_cast<const float2*>(p);
            float2 v1 = *reinterpret_cast<const float2*>(p + 8);
            bb[g][0] = bpack(v0.x, v0.y);
            bb[g][1] = bpack(v1.x, v1.y);
        }
#pragma unroll
        for (int f = 0; f < 4; ++f)
#pragma unroll
            for (int g = 0; g < 4; ++g) mma16816(acc[f][g], a[f], bb[g]);
    }
}

__global__ __launch_bounds__(256, 2) void bilinear_gemm(const float* __restrict__ Wp) {
    extern __shared__ uint32_t smem[];
    float* Bsf = reinterpret_cast<float*>(smem);
    uint32_t* Ts = smem + SM_TS_OFF;
    uint32_t* img_s = smem + SM_IMG_OFF;

    int tid = threadIdx.x;
    int lane = tid & 31, warp = tid >> 5;
    int wm = warp >> 2, wn = warp & 3;   // 2 x 4 warp grid, warp tile 64x32
    int s = blockIdx.x, nt = blockIdx.y, mt = blockIdx.z;
    int b0 = mt * BM, k0 = nt * BN;

    int kb = (int)(((long)ITERS * s) / SPLITS);
    int ke = (int)(((long)ITERS * (s + 1)) / SPLITS);
    int n_it = ke - kb;

    // ---- cp.async assignment: thread -> 4 x 16B per chunk ----
    int crow = tid >> 3, cseg = tid & 7;
    const float* wp_src[4];
    uint32_t sm_off[4];
#pragma unroll
    for (int u = 0; u < 4; ++u) {
        int row = crow + 32 * u;
        wp_src[u] = Wp + (size_t)(k0 + row) * KIJ + cseg * 4;
        sm_off[u] = (uint32_t)(row * BSF + cseg * 4) * 4u;
    }
    uint32_t bs_addr = smem_u32(smem);

#define CPY(chunk)                                                            \
    do {                                                                      \
        if ((chunk) < ke) {                                                   \
            size_t off_ = (size_t)((chunk) & 511) * 512 +                     \
                          (size_t)((chunk) >> 9) * 32;                        \
            uint32_t sa_ = bs_addr + (uint32_t)(((chunk) & (NSTG - 1)) *      \
                                                (STG_U32 * 4));               \
            _Pragma("unroll") for (int u_ = 0; u_ < 4; ++u_) {                \
                asm volatile("cp.async.cg.shared.global [%0], [%1], 16;"      \
                             :: "r"(sa_ + sm_off[u_]), "l"(wp_src[u_] + off_)); \
            }                                                                 \
        }                                                                     \
        asm volatile("cp.async.commit_group;" ::: "memory");                  \
    } while (0)

#define TS_LOAD(jb)                                                           \
    do {                                                                      \
        _Pragma("unroll") for (int w_ = 0; w_ < 2; ++w_) {                    \
            int idx_ = tid + 256 * w_;                                        \
            int r_ = idx_ >> 2, u4_ = idx_ & 3;                               \
            uint4 v_ = *reinterpret_cast<const uint4*>(                       \
                g_txtb + (size_t)(b0 + r_) * 512 + (jb) * 32 + u4_ * 8);      \
            *reinterpret_cast<uint4*>(&Ts[r_ * TSTR + u4_ * 4]) = v_;         \
        }                                                                     \
    } while (0)

    // ---- prologue: first 3 B chunks, txt block, img cols kb..kb+2 ----
    CPY(kb);
    CPY(kb + 1);
    CPY(kb + 2);

    int cur_jblk = kb >> 9;
    TS_LOAD(cur_jblk);

    uint32_t ir_next = 0, ir_far = 0;
    if (tid < 128) {
        img_s[(kb & 1) * 128 + tid] = g_imgu[(kb & 511) * 256 + b0 + tid];
        if (kb + 1 < ITERS) ir_next = g_imgu[((kb + 1) & 511) * 256 + b0 + tid];
        if (kb + 2 < ITERS) ir_far  = g_imgu[((kb + 2) & 511) * 256 + b0 + tid];
    }

    float acc[4][4][4];
#pragma unroll
    for (int f = 0; f < 4; ++f)
#pragma unroll
        for (int g = 0; g < 4; ++g)
#pragma unroll
            for (int e = 0; e < 4; ++e) acc[f][g][e] = 0.f;

    int arow[8];
#pragma unroll
    for (int f = 0; f < 4; ++f) {
        arow[2 * f] = wm * 64 + f * 16 + (lane >> 2);
        arow[2 * f + 1] = arow[2 * f] + 8;
    }

    // ---- main loop: 1 sync/iter, cp.async depth 3, 2-iter img prefetch ----
#pragma unroll 1
    for (int r = 0; r < n_it; ++r) {
        int c = kb + r;
        asm volatile("cp.async.wait_group 2;" ::: "memory");
        __syncthreads();

        if ((c >> 9) != cur_jblk) {       // <=2 times per CTA
            cur_jblk = c >> 9;
            TS_LOAD(cur_jblk);
            __syncthreads();
        }

        CPY(c + 3);

        if (tid < 128) {
            img_s[((c + 1) & 1) * 128 + tid] = ir_next;
            ir_next = ir_far;
            if (c + 3 < ITERS) ir_far = g_imgu[((c + 3) & 511) * 256 + b0 + tid];
        }

        compute_iter(Bsf + (c & (NSTG - 1)) * STG_U32, Ts,
                     img_s + (c & 1) * 128, arow, lane, wn, acc);
    }
    asm volatile("cp.async.wait_group 0;" ::: "memory");

    // ---- split-K epilogue ----
#pragma unroll
    for (int f = 0; f < 4; ++f)
#pragma unroll
        for (int g = 0; g < 4; ++g)
#pragma unroll
            for (int e = 0; e < 4; ++e) {
                int rr = b0 + wm * 64 + f * 16 + (lane >> 2) + ((e >> 1) << 3);
                int cc = k0 + wn * 32 + g * 8 + ((lane & 3) << 1) + (e & 1);
                atomicAdd(&g_feats[rr * 512 + cc], acc[f][g][e]);
            }
#undef CPY
#undef TS_LOAD
}

// ------------------ stage 4: bias + relu + classifier + sigmoid -------------
__global__ __launch_bounds__(128) void final_k(const float* __restrict__ bp,
                                               const float* __restrict__ Wc,
                                               const float* __restrict__ bc,
                                               float* __restrict__ out) {
    int b = blockIdx.x;
    int t = threadIdx.x;
    float p = 0.f;
    for (int k = t; k < 512; k += 128) {
        float f = g_feats[b * 512 + k] + bp[k];
        f = fmaxf(f, 0.f);
        p += f * Wc[k];
    }
#pragma unroll
    for (int o = 16; o > 0; o >>= 1) p += __shfl_xor_sync(0xffffffffu, p, o);
    __shared__ float sr[4];
    if ((t & 31) == 0) sr[t >> 5] = p;
    __syncthreads();
    if (t == 0) {
        float logit = sr[0] + sr[1] + sr[2] + sr[3] + bc[0];
        out[b] = 1.f / (1.f + expf(-logit));
    }
}

// ------------------------------ launcher ------------------------------------
extern "C" void kernel_launch(void* const* d_in, const int* in_sizes, int n_in,
                              void* d_out, int out_size) {
    const float* img_e = (const float*)d_in[0];
    const float* txt_e = (const float*)d_in[1];
    const float* Wi = (const float*)d_in[2];
    const float* bi = (const float*)d_in[3];
    const float* Wt = (const float*)d_in[4];
    const float* bt = (const float*)d_in[5];
    const float* Wp = (const float*)d_in[6];
    const float* bp = (const float*)d_in[7];
    const float* Wc = (const float*)d_in[8];
    const float* bc = (const float*)d_in[9];
    float* out = (float*)d_out;

    cudaFuncSetAttribute(bilinear_gemm, cudaFuncAttributeMaxDynamicSharedMemorySize,
                         SM_BYTES);

    map_gemm2<<<dim3(16, 8, 2), 256>>>(img_e, txt_e, Wi, bi, Wt, bt);
    norm_zero<<<512, 128>>>();
    bilinear_gemm<<<dim3(SPLITS, 4, 2), 256, SM_BYTES>>>(Wp);
    final_k<<<256, 128>>>(bp, Wc, bc, out);
}

// round 10
// speedup vs baseline: 2.2543x; 1.0136x over previous
#include <cuda_runtime.h>
#include <cuda_bf16.h>
#include <cstdint>

// ---------------------------------------------------------------------------
// CustomBLIP: sigmoid( relu( bilinear(img_n, txt_n; Wp) + bp ) @ Wc^T + bc )
// Core: feats[b,k] = sum_ij (img[b,i]*txt[b,j]) * Wp[k, i*512+j]
//   -> GEMM C[256,512] = A[256,262144] x Wp^T, A generated on the fly.
// R9: txt operands hoisted to registers per j-block segment (kills 16 LDS.32
//     per thread per iter); cp.async ring deepened to 5 stages (lookahead 4).
//     2 CTAs/SM preserved (111KB smem, <=128 regs).
// ---------------------------------------------------------------------------

#define B_SZ   256
#define M_DIM  512
#define KIJ    (512 * 512)          // 262144
#define ITERS  8192                 // chunks of 32 ij
#define BM     128
#define BN     128
#define SPLITS 37                   // 37*4*2 = 296 CTAs = 2/SM

#define NSTG    5                   // cp.async stages
#define BSF     40                  // Wp smem row stride in fp32 (32 + pad)
#define STG_U32 (BN * BSF)          // 5120 u32 per stage
#define TSTR    20                  // txt smem row stride in u32 (16 + pad)

// smem layout (u32): Bs[5][STG_U32] | Ts[128*TSTR] | img_s[2][128]
#define SM_TS_OFF   (NSTG * STG_U32)                // 25600
#define SM_IMG_OFF  (SM_TS_OFF + BM * TSTR)         // 28160
#define SM_U32_TOT  (SM_IMG_OFF + 256)              // 28416
#define SM_BYTES    (SM_U32_TOT * 4)                // 113664 -> 2 CTAs/SM

// -------------------------------- scratch ---------------------------------
__device__ float                        g_pre[2 * B_SZ * M_DIM];
__device__ uint32_t                     g_imgu[M_DIM * B_SZ];  // [i][b] bf16x2 bcast
__device__ __align__(16) __nv_bfloat16  g_txtb[B_SZ * M_DIM];  // [b][j]
__device__ float                        g_feats[B_SZ * M_DIM];

// -------------------------------- helpers ---------------------------------
__device__ __forceinline__ uint32_t u32_of(__nv_bfloat162 v) {
    return *reinterpret_cast<uint32_t*>(&v);
}
__device__ __forceinline__ __nv_bfloat162 bf2_of(uint32_t v) {
    return *reinterpret_cast<__nv_bfloat162*>(&v);
}
__device__ __forceinline__ uint32_t hmul2u(uint32_t a, uint32_t b) {
    __nv_bfloat162 r = __hmul2(bf2_of(a), bf2_of(b));
    return u32_of(r);
}
__device__ __forceinline__ uint32_t bpack(float lo, float hi) {
    __nv_bfloat162 h = __floats2bfloat162_rn(lo, hi);
    return u32_of(h);
}
__device__ __forceinline__ uint32_t smem_u32(const void* p) {
    uint32_t a;
    asm("{ .reg .u64 t; cvta.to.shared.u64 t, %1; cvt.u32.u64 %0, t; }"
        : "=r"(a) : "l"(p));
    return a;
}
__device__ __forceinline__ void mma16816(float* d, const uint32_t* a, const uint32_t* b) {
    asm volatile(
        "mma.sync.aligned.m16n8k16.row.col.f32.bf16.bf16.f32 "
        "{%0,%1,%2,%3}, {%4,%5,%6,%7}, {%8,%9}, {%0,%1,%2,%3};\n"
        : "+f"(d[0]), "+f"(d[1]), "+f"(d[2]), "+f"(d[3])
        : "r"(a[0]), "r"(a[1]), "r"(a[2]), "r"(a[3]), "r"(b[0]), "r"(b[1]));
}

// ----------------------- stage 1: mapping GEMMs (both paths) ----------------
__global__ __launch_bounds__(256) void map_gemm2(const float* __restrict__ Ximg,
                                                 const float* __restrict__ Xtxt,
                                                 const float* __restrict__ Wi,
                                                 const float* __restrict__ bi,
                                                 const float* __restrict__ Wt,
                                                 const float* __restrict__ bt) {
    __shared__ float Xs[32][33];
    __shared__ float Ws[32][33];
    int path = blockIdx.z;
    const float* X = path == 0 ? Ximg : Xtxt;
    const float* W = path == 0 ? Wi : Wt;
    const float* bias = path == 0 ? bi : bt;
    int tid = threadIdx.x;
    int tx = tid & 31, ty = tid >> 5;
    int mt = blockIdx.x, bt_ = blockIdx.y;
    float acc[4] = {0.f, 0.f, 0.f, 0.f};
    for (int d0 = 0; d0 < 512; d0 += 32) {
#pragma unroll
        for (int q = 0; q < 4; ++q) {
            int idx = tid + 256 * q;
            int r = idx >> 5, c = idx & 31;
            Xs[r][c] = X[(bt_ * 32 + r) * 512 + d0 + c];
            Ws[r][c] = W[(mt * 32 + r) * 512 + d0 + c];
        }
        __syncthreads();
#pragma unroll
        for (int kk = 0; kk < 32; ++kk) {
            float w = Ws[tx][kk];
#pragma unroll
            for (int r = 0; r < 4; ++r) acc[r] += Xs[ty + 8 * r][kk] * w;
        }
        __syncthreads();
    }
    float bb = bias[mt * 32 + tx];
#pragma unroll
    for (int r = 0; r < 4; ++r)
        g_pre[path * (B_SZ * M_DIM) + (bt_ * 32 + ty + 8 * r) * 512 + mt * 32 + tx] =
            acc[r] + bb;
}

// ----- stage 2: L2 normalize; img -> transposed bf16x2 table; txt -> bf16 ---
__global__ __launch_bounds__(128) void norm_zero() {
    int bx = blockIdx.x;
    int path = bx >> 8;
    int row = bx & 255;
    int t = threadIdx.x;
    const float* src = g_pre + path * (B_SZ * M_DIM) + row * 512;
    float v[4];
    float ss = 0.f;
#pragma unroll
    for (int q = 0; q < 4; ++q) {
        v[q] = src[t + 128 * q];
        ss += v[q] * v[q];
    }
#pragma unroll
    for (int o = 16; o > 0; o >>= 1) ss += __shfl_xor_sync(0xffffffffu, ss, o);
    __shared__ float sred[4];
    if ((t & 31) == 0) sred[t >> 5] = ss;
    __syncthreads();
    float tot = sred[0] + sred[1] + sred[2] + sred[3];
    float sc = 1.f / fmaxf(sqrtf(tot), 1e-12f);
    if (path == 0) {
#pragma unroll
        for (int q = 0; q < 4; ++q) {
            float val = v[q] * sc;
            g_imgu[(t + 128 * q) * 256 + row] = bpack(val, val);
            g_feats[row * 512 + t + 128 * q] = 0.f;
        }
    } else {
#pragma unroll
        for (int q = 0; q < 4; ++q)
            g_txtb[row * 512 + t + 128 * q] = __float2bfloat16(v[q] * sc);
    }
}

// --------------------- stage 3: the big bilinear GEMM -----------------------
// chunk c in [0,8192): i = c & 511 (fast), jblk = c >> 9 (slow, 16 blocks)
__global__ __launch_bounds__(256, 2) void bilinear_gemm(const float* __restrict__ Wp) {
    extern __shared__ uint32_t smem[];
    float* Bsf = reinterpret_cast<float*>(smem);
    uint32_t* Ts = smem + SM_TS_OFF;
    uint32_t* img_s = smem + SM_IMG_OFF;

    int tid = threadIdx.x;
    int lane = tid & 31, warp = tid >> 5;
    int wm = warp >> 2, wn = warp & 3;   // 2 x 4 warp grid, warp tile 64x32
    int s = blockIdx.x, nt = blockIdx.y, mt = blockIdx.z;
    int b0 = mt * BM, k0 = nt * BN;

    int kb = (int)(((long)ITERS * s) / SPLITS);
    int ke = (int)(((long)ITERS * (s + 1)) / SPLITS);

    // ---- cp.async assignment: thread -> 4 x 16B per chunk ----
    int crow = tid >> 3, cseg = tid & 7;
    const float* wp_src[4];
    uint32_t sm_off[4];
#pragma unroll
    for (int u = 0; u < 4; ++u) {
        int row = crow + 32 * u;
        wp_src[u] = Wp + (size_t)(k0 + row) * KIJ + cseg * 4;
        sm_off[u] = (uint32_t)(row * BSF + cseg * 4) * 4u;
    }
    uint32_t bs_addr = smem_u32(smem);

#define CPY(chunk, stg)                                                       \
    do {                                                                      \
        if ((chunk) < ke) {                                                   \
            size_t off_ = (size_t)((chunk) & 511) * 512 +                     \
                          (size_t)((chunk) >> 9) * 32;                        \
            uint32_t sa_ = bs_addr + (uint32_t)((stg) * (STG_U32 * 4));       \
            _Pragma("unroll") for (int u_ = 0; u_ < 4; ++u_) {                \
                asm volatile("cp.async.cg.shared.global [%0], [%1], 16;"      \
                             :: "r"(sa_ + sm_off[u_]), "l"(wp_src[u_] + off_)); \
            }                                                                 \
        }                                                                     \
        asm volatile("cp.async.commit_group;" ::: "memory");                  \
    } while (0)

#define TS_LOAD(jb)                                                           \
    do {                                                                      \
        _Pragma("unroll") for (int w_ = 0; w_ < 2; ++w_) {                    \
            int idx_ = tid + 256 * w_;                                        \
            int r_ = idx_ >> 2, u4_ = idx_ & 3;                               \
            uint4 v_ = *reinterpret_cast<const uint4*>(                       \
                g_txtb + (size_t)(b0 + r_) * 512 + (jb) * 32 + u4_ * 8);      \
            *reinterpret_cast<uint4*>(&Ts[r_ * TSTR + u4_ * 4]) = v_;         \
        }                                                                     \
    } while (0)

    // ---- prologue: 4 B chunks in flight, img cols kb..kb+2 ----
    CPY(kb, 0);
    CPY(kb + 1, 1);
    CPY(kb + 2, 2);
    CPY(kb + 3, 3);

    uint32_t ir_next = 0, ir_far = 0;
    if (tid < 128) {
        img_s[(kb & 1) * 128 + tid] = g_imgu[(kb & 511) * 256 + b0 + tid];
        if (kb + 1 < ITERS) ir_next = g_imgu[((kb + 1) & 511) * 256 + b0 + tid];
        if (kb + 2 < ITERS) ir_far  = g_imgu[((kb + 2) & 511) * 256 + b0 + tid];
    }

    float acc[4][4][4];
#pragma unroll
    for (int f = 0; f < 4; ++f)
#pragma unroll
        for (int g = 0; g < 4; ++g)
#pragma unroll
            for (int e = 0; e < 4; ++e) acc[f][g][e] = 0.f;

    int arow[8];
#pragma unroll
    for (int f = 0; f < 4; ++f) {
        arow[2 * f] = wm * 64 + f * 16 + (lane >> 2);
        arow[2 * f + 1] = arow[2 * f] + 8;
    }

    int c = kb;
    int st = 0;                       // stage of current chunk
    int stp = 4;                      // stage for chunk c+4

    // ---- segmented main loop: txt regs constant within a j-block ----
#pragma unroll 1
    while (c < ke) {
        int jb = c >> 9;
        int seg_end = (jb + 1) << 9;
        if (seg_end > ke) seg_end = ke;

        TS_LOAD(jb);
        __syncthreads();

        // hoist this thread's txt operands into registers (16 u32)
        uint32_t treg[2][4][4];
#pragma unroll
        for (int k2 = 0; k2 < 2; ++k2) {
            int co = k2 * 8 + (lane & 3);
#pragma unroll
            for (int f = 0; f < 4; ++f) {
                const uint32_t* r0 = Ts + arow[2 * f] * TSTR;
                const uint32_t* r1 = Ts + arow[2 * f + 1] * TSTR;
                treg[k2][f][0] = r0[co];
                treg[k2][f][1] = r1[co];
                treg[k2][f][2] = r0[co + 4];
                treg[k2][f][3] = r1[co + 4];
            }
        }

#pragma unroll 1
        for (; c < seg_end; ++c) {
            asm volatile("cp.async.wait_group 3;" ::: "memory");
            __syncthreads();

            CPY(c + 4, stp);

            if (tid < 128) {
                img_s[((c + 1) & 1) * 128 + tid] = ir_next;
                ir_next = ir_far;
                if (c + 3 < ITERS)
                    ir_far = g_imgu[((c + 3) & 511) * 256 + b0 + tid];
            }

            // ---- compute chunk c ----
            {
                const float* bsf = Bsf + st * STG_U32;
                const uint32_t* imgcol = img_s + (c & 1) * 128;
#pragma unroll
                for (int k2 = 0; k2 < 2; ++k2) {
                    uint32_t a[4][4];
#pragma unroll
                    for (int f = 0; f < 4; ++f) {
                        uint32_t im0 = imgcol[arow[2 * f]];
                        uint32_t im1 = imgcol[arow[2 * f + 1]];
                        a[f][0] = hmul2u(treg[k2][f][0], im0);
                        a[f][1] = hmul2u(treg[k2][f][1], im1);
                        a[f][2] = hmul2u(treg[k2][f][2], im0);
                        a[f][3] = hmul2u(treg[k2][f][3], im1);
                    }
                    uint32_t bb[4][2];
#pragma unroll
                    for (int g = 0; g < 4; ++g) {
                        int n = wn * 32 + g * 8 + (lane >> 2);
                        const float* p = bsf + n * BSF + k2 * 16 + (lane & 3) * 2;
                        float2 v0 = *reinterpret_cast<const float2*>(p);
                        float2 v1 = *reinterpret_cast<const float2*>(p + 8);
                        bb[g][0] = bpack(v0.x, v0.y);
                        bb[g][1] = bpack(v1.x, v1.y);
                    }
#pragma unroll
                    for (int f = 0; f < 4; ++f)
#pragma unroll
                        for (int g = 0; g < 4; ++g) mma16816(acc[f][g], a[f], bb[g]);
                }
            }

            st = (st == NSTG - 1) ? 0 : st + 1;
            stp = (stp == NSTG - 1) ? 0 : stp + 1;
        }
    }
    asm volatile("cp.async.wait_group 0;" ::: "memory");

    // ---- split-K epilogue ----
#pragma unroll
    for (int f = 0; f < 4; ++f)
#pragma unroll
        for (int g = 0; g < 4; ++g)
#pragma unroll
            for (int e = 0; e < 4; ++e) {
                int rr = b0 + wm * 64 + f * 16 + (lane >> 2) + ((e >> 1) << 3);
                int cc = k0 + wn * 32 + g * 8 + ((lane & 3) << 1) + (e & 1);
                atomicAdd(&g_feats[rr * 512 + cc], acc[f][g][e]);
            }
#undef CPY
#undef TS_LOAD
}

// ------------------ stage 4: bias + relu + classifier + sigmoid -------------
__global__ __launch_bounds__(128) void final_k(const float* __restrict__ bp,
                                               const float* __restrict__ Wc,
                                               const float* __restrict__ bc,
                                               float* __restrict__ out) {
    int b = blockIdx.x;
    int t = threadIdx.x;
    float p = 0.f;
    for (int k = t; k < 512; k += 128) {
        float f = g_feats[b * 512 + k] + bp[k];
        f = fmaxf(f, 0.f);
        p += f * Wc[k];
    }
#pragma unroll
    for (int o = 16; o > 0; o >>= 1) p += __shfl_xor_sync(0xffffffffu, p, o);
    __shared__ float sr[4];
    if ((t & 31) == 0) sr[t >> 5] = p;
    __syncthreads();
    if (t == 0) {
        float logit = sr[0] + sr[1] + sr[2] + sr[3] + bc[0];
        out[b] = 1.f / (1.f + expf(-logit));
    }
}

// ------------------------------ launcher ------------------------------------
extern "C" void kernel_launch(void* const* d_in, const int* in_sizes, int n_in,
                              void* d_out, int out_size) {
    const float* img_e = (const float*)d_in[0];
    const float* txt_e = (const float*)d_in[1];
    const float* Wi = (const float*)d_in[2];
    const float* bi = (const float*)d_in[3];
    const float* Wt = (const float*)d_in[4];
    const float* bt = (const float*)d_in[5];
    const float* Wp = (const float*)d_in[6];
    const float* bp = (const float*)d_in[7];
    const float* Wc = (const float*)d_in[8];
    const float* bc = (const float*)d_in[9];
    float* out = (float*)d_out;

    cudaFuncSetAttribute(bilinear_gemm, cudaFuncAttributeMaxDynamicSharedMemorySize,
                         SM_BYTES);

    map_gemm2<<<dim3(16, 8, 2), 256>>>(img_e, txt_e, Wi, bi, Wt, bt);
    norm_zero<<<512, 128>>>();
    bilinear_gemm<<<dim3(SPLITS, 4, 2), 256, SM_BYTES>>>(Wp);
    final_k<<<256, 128>>>(bp, Wc, bc, out);
}